// round 4
// baseline (speedup 1.0000x reference)
#include <cuda_runtime.h>
#include <cuda_bf16.h>
#include <math.h>

// ---------------- problem constants ----------------
#define B_   32
#define S_   128
#define E_   300
#define C_   100
#define EC_  50
#define LC_  50
#define H_   256
#define L_   17
#define G4_  1024          // 4*H
#define D_   400           // E + C

// ---------------- scratch (device globals; no allocation allowed) ----------------
__device__ float g_conv1[B_ * C_ * 48];
__device__ float g_conv2[B_ * C_ * 45];
__device__ float g_pooled[B_ * C_];
__device__ float g_gpool[2 * B_ * G4_];                 // bias + pooled @ w_ih[:,300:]
__device__ float g_gin[2 * S_ * B_ * G4_];              // input preactivations [dir][s*32+b][1024]
__device__ float g_hseq[2 * S_ * B_ * H_];              // LSTM outputs [dir][s][b][256]
__device__ float g_cst[2 * B_ * H_];                    // running cell state [dir][b][256]
__device__ float g_em[B_ * L_ * S_];                    // emissions [b][l][s]

__device__ __forceinline__ float sigm(float x) { return 1.f / (1.f + expf(-x)); }

// ---------------- char CNN ----------------
__global__ void __launch_bounds__(128) conv1_kernel(const int* __restrict__ xc,
                                                    const float* __restrict__ cemb,
                                                    const float* __restrict__ w1,
                                                    const float* __restrict__ b1) {
    int b = blockIdx.x;
    int oc0 = blockIdx.y * 25;
    __shared__ float ce[EC_][LC_];
    int tid = threadIdx.x;
    for (int i = tid; i < EC_ * LC_; i += 128) {
        int e = i / LC_, t = i % LC_;
        ce[e][t] = cemb[xc[b * LC_ + t] * EC_ + e];
    }
    __syncthreads();
    for (int i = tid; i < 25 * 48; i += 128) {
        int o = i / 48, t = i % 48;
        const float* wr = w1 + (size_t)(oc0 + o) * (EC_ * 3);
        float acc = b1[oc0 + o];
        for (int e = 0; e < EC_; e++) {
            acc += ce[e][t + 0] * wr[e * 3 + 0];
            acc += ce[e][t + 1] * wr[e * 3 + 1];
            acc += ce[e][t + 2] * wr[e * 3 + 2];
        }
        g_conv1[b * (C_ * 48) + (oc0 + o) * 48 + t] = fmaxf(acc, 0.f);
    }
}

__global__ void __launch_bounds__(128) conv2_kernel(const float* __restrict__ w2,
                                                    const float* __restrict__ b2) {
    int b = blockIdx.x;
    int oc0 = blockIdx.y * 25;
    __shared__ float in_s[C_][48];
    int tid = threadIdx.x;
    for (int i = tid; i < C_ * 48; i += 128) ((float*)in_s)[i] = g_conv1[b * (C_ * 48) + i];
    __syncthreads();
    for (int i = tid; i < 25 * 45; i += 128) {
        int o = i / 45, t = i % 45;
        const float* wr = w2 + (size_t)(oc0 + o) * (C_ * 4);
        float acc = b2[oc0 + o];
        for (int ic = 0; ic < C_; ic++) {
            acc += in_s[ic][t + 0] * wr[ic * 4 + 0];
            acc += in_s[ic][t + 1] * wr[ic * 4 + 1];
            acc += in_s[ic][t + 2] * wr[ic * 4 + 2];
            acc += in_s[ic][t + 3] * wr[ic * 4 + 3];
        }
        g_conv2[b * (C_ * 45) + (oc0 + o) * 45 + t] = fmaxf(acc, 0.f);
    }
}

__global__ void __launch_bounds__(128) conv3_kernel(const float* __restrict__ w3,
                                                    const float* __restrict__ b3) {
    int b = blockIdx.x;
    int oc0 = blockIdx.y * 25;
    __shared__ float in_s[C_][45];
    __shared__ float out_s[25][41];
    int tid = threadIdx.x;
    for (int i = tid; i < C_ * 45; i += 128) ((float*)in_s)[i] = g_conv2[b * (C_ * 45) + i];
    __syncthreads();
    for (int i = tid; i < 25 * 41; i += 128) {
        int o = i / 41, t = i % 41;
        const float* wr = w3 + (size_t)(oc0 + o) * (C_ * 5);
        float acc = b3[oc0 + o];
        for (int ic = 0; ic < C_; ic++) {
            acc += in_s[ic][t + 0] * wr[ic * 5 + 0];
            acc += in_s[ic][t + 1] * wr[ic * 5 + 1];
            acc += in_s[ic][t + 2] * wr[ic * 5 + 2];
            acc += in_s[ic][t + 3] * wr[ic * 5 + 3];
            acc += in_s[ic][t + 4] * wr[ic * 5 + 4];
        }
        out_s[o][t] = fmaxf(acc, 0.f);
    }
    __syncthreads();
    if (tid < 25) {
        float m = out_s[tid][0];
        for (int t = 1; t < 41; t++) m = fmaxf(m, out_s[tid][t]);
        g_pooled[b * C_ + oc0 + tid] = m;
    }
}

// ---------------- pooled contribution + bias ----------------
__global__ void __launch_bounds__(256) gpool_kernel(const float* __restrict__ w_ih_f,
                                                    const float* __restrict__ w_ih_b,
                                                    const float* __restrict__ b_f,
                                                    const float* __restrict__ b_b) {
    int dir = blockIdx.x;
    int b = blockIdx.y;
    const float* W = dir ? w_ih_b : w_ih_f;
    const float* bias = dir ? b_b : b_f;
    __shared__ float p[C_];
    int tid = threadIdx.x;
    if (tid < C_) p[tid] = g_pooled[b * C_ + tid];
    __syncthreads();
    for (int r = tid; r < G4_; r += 256) {
        const float* wr = W + (size_t)r * D_ + E_;
        float acc = bias[r];
        #pragma unroll 4
        for (int k = 0; k < C_; k++) acc += p[k] * wr[k];
        g_gpool[dir * (B_ * G4_) + b * G4_ + r] = acc;
    }
}

// ---------------- input GEMM: gin[dir][s*32+b][r] ----------------
__global__ void __launch_bounds__(256) gemm_input_kernel(const int* __restrict__ x,
                                                         const float* __restrict__ word_emb,
                                                         const float* __restrict__ w_ih_f,
                                                         const float* __restrict__ w_ih_b) {
    const int dir = blockIdx.z;
    const float* __restrict__ W = dir ? w_ih_b : w_ih_f;
    float* __restrict__ out = g_gin + (size_t)dir * (S_ * B_ * G4_);
    const float* __restrict__ gp = g_gpool + dir * (B_ * G4_);
    const int m0 = blockIdx.y * 128;
    const int n0 = blockIdx.x * 128;
    __shared__ float As[16][132];
    __shared__ float Bs[16][132];
    __shared__ int wid[128];
    const int tid = threadIdx.x;
    if (tid < 128) {
        int m = m0 + tid;
        wid[tid] = x[(m & 31) * S_ + (m >> 5)];   // b = m&31, s = m>>5
    }
    __syncthreads();
    const int tx = tid & 15, ty = tid >> 4;
    float acc[8][8];
    #pragma unroll
    for (int i = 0; i < 8; i++)
        #pragma unroll
        for (int j = 0; j < 8; j++) acc[i][j] = 0.f;

    for (int k0 = 0; k0 < 304; k0 += 16) {
        #pragma unroll
        for (int l = 0; l < 2; l++) {
            int idx = tid + l * 256;
            int row = idx >> 2;
            int kq = (idx & 3) * 4;
            int k = k0 + kq;
            float4 av = make_float4(0.f, 0.f, 0.f, 0.f);
            if (k < 300)
                av = *reinterpret_cast<const float4*>(word_emb + (size_t)wid[row] * E_ + k);
            As[kq + 0][row] = av.x;
            As[kq + 1][row] = av.y;
            As[kq + 2][row] = av.z;
            As[kq + 3][row] = av.w;
            float4 bv = *reinterpret_cast<const float4*>(W + (size_t)(n0 + row) * D_ + k);
            Bs[kq + 0][row] = bv.x;
            Bs[kq + 1][row] = bv.y;
            Bs[kq + 2][row] = bv.z;
            Bs[kq + 3][row] = bv.w;
        }
        __syncthreads();
        #pragma unroll
        for (int kk = 0; kk < 16; kk++) {
            float a[8], bq[8];
            #pragma unroll
            for (int i = 0; i < 8; i++) a[i] = As[kk][ty * 8 + i];
            #pragma unroll
            for (int j = 0; j < 8; j++) bq[j] = Bs[kk][tx * 8 + j];
            #pragma unroll
            for (int i = 0; i < 8; i++)
                #pragma unroll
                for (int j = 0; j < 8; j++) acc[i][j] += a[i] * bq[j];
        }
        __syncthreads();
    }
    #pragma unroll
    for (int i = 0; i < 8; i++) {
        int m = m0 + ty * 8 + i;
        int bb = m & 31;
        float* orow = out + (size_t)m * G4_;
        const float* gpr = gp + bb * G4_;
        #pragma unroll
        for (int j = 0; j < 8; j++) {
            int n = n0 + tx * 8 + j;
            orow[n] = acc[i][j] + gpr[n];
        }
    }
}

// ---------------- LSTM: one kernel launch per timestep ----------------
__global__ void __launch_bounds__(128) cinit_kernel(const float* __restrict__ c0) {
    int i = blockIdx.x * 128 + threadIdx.x;
    g_cst[i] = c0[i];
}

__global__ void __launch_bounds__(128) lstm_step_kernel(const float* __restrict__ w_hh_f,
                                                        const float* __restrict__ w_hh_b,
                                                        const float* __restrict__ h0,
                                                        int t) {
    const int dir = blockIdx.y;
    const int j0 = blockIdx.x * 4;
    const int s = dir ? (S_ - 1 - t) : t;
    const int sp = dir ? (s + 1) : (s - 1);
    const float* __restrict__ W = dir ? w_hh_b : w_hh_f;
    const float* __restrict__ hprev =
        (t == 0) ? (h0 + dir * (B_ * H_))
                 : (g_hseq + (size_t)dir * (S_ * B_ * H_) + (size_t)sp * (B_ * H_));
    __shared__ float hs[H_][33];
    const int tid = threadIdx.x;
    for (int idx = tid; idx < B_ * H_; idx += 128) {
        int b = idx >> 8, k = idx & 255;
        hs[k][b] = hprev[idx];
    }
    __syncthreads();
    const int u = tid >> 5;
    const int b = tid & 31;
    const int unit = j0 + u;
    float acc0 = 0.f, acc1 = 0.f, acc2 = 0.f, acc3 = 0.f;
    const float4* w0 = (const float4*)(W + (size_t)(0 * H_ + unit) * H_);
    const float4* w1 = (const float4*)(W + (size_t)(1 * H_ + unit) * H_);
    const float4* w2 = (const float4*)(W + (size_t)(2 * H_ + unit) * H_);
    const float4* w3 = (const float4*)(W + (size_t)(3 * H_ + unit) * H_);
    #pragma unroll 4
    for (int kc = 0; kc < 64; kc++) {
        float ha = hs[kc * 4 + 0][b];
        float hb = hs[kc * 4 + 1][b];
        float hc = hs[kc * 4 + 2][b];
        float hd = hs[kc * 4 + 3][b];
        float4 a = __ldg(&w0[kc]);
        acc0 += a.x * ha + a.y * hb + a.z * hc + a.w * hd;
        float4 f = __ldg(&w1[kc]);
        acc1 += f.x * ha + f.y * hb + f.z * hc + f.w * hd;
        float4 g = __ldg(&w2[kc]);
        acc2 += g.x * ha + g.y * hb + g.z * hc + g.w * hd;
        float4 o = __ldg(&w3[kc]);
        acc3 += o.x * ha + o.y * hb + o.z * hc + o.w * hd;
    }
    const float* grow = g_gin + (size_t)dir * (S_ * B_ * G4_) + (size_t)s * (B_ * G4_) + b * G4_;
    float gi = acc0 + grow[0 * H_ + unit];
    float gf = acc1 + grow[1 * H_ + unit];
    float gg = acc2 + grow[2 * H_ + unit];
    float go = acc3 + grow[3 * H_ + unit];
    float* cp = g_cst + dir * (B_ * H_) + b * H_ + unit;
    float c = sigm(gf) * (*cp) + sigm(gi) * tanhf(gg);
    *cp = c;
    g_hseq[(size_t)dir * (S_ * B_ * H_) + (size_t)s * (B_ * H_) + b * H_ + unit] =
        sigm(go) * tanhf(c);
}

// ---------------- fc -> emission logits (layout [b][l][s]) ----------------
__global__ void __launch_bounds__(256) fc_kernel(const float* __restrict__ fc_w,
                                                 const float* __restrict__ fc_b) {
    const int s = blockIdx.x;
    __shared__ float ws[L_ * 512];
    const int tid = threadIdx.x;
    for (int i = tid; i < L_ * 512; i += 256) ws[i] = fc_w[i];
    __syncthreads();
    const float* hf = g_hseq + (size_t)s * (B_ * H_);
    const float* hb = g_hseq + (size_t)(S_ * B_ * H_) + (size_t)s * (B_ * H_);
    for (int idx = tid; idx < B_ * L_; idx += 256) {
        int b = idx / L_, l = idx % L_;
        const float4* hf4 = (const float4*)(hf + b * H_);
        const float4* hb4 = (const float4*)(hb + b * H_);
        const float4* w0 = (const float4*)(ws + l * 512);
        const float4* w1 = w0 + 64;
        float acc = fc_b[l];
        #pragma unroll 8
        for (int k = 0; k < 64; k++) {
            float4 h4 = hf4[k], w4 = w0[k];
            acc += h4.x * w4.x + h4.y * w4.y + h4.z * w4.z + h4.w * w4.w;
            float4 h5 = hb4[k], w5 = w1[k];
            acc += h5.x * w5.x + h5.y * w5.y + h5.z * w5.z + h5.w * w5.w;
        }
        g_em[b * (L_ * S_) + l * S_ + s] = acc;
    }
}

// ---------------- softmax over seq dim ----------------
__global__ void __launch_bounds__(256) softmax_kernel() {
    int w = (blockIdx.x * 256 + threadIdx.x) >> 5;
    int lane = threadIdx.x & 31;
    if (w >= B_ * L_) return;
    float* row = g_em + (size_t)w * S_;
    float v[4];
    float mx = -1e30f;
    #pragma unroll
    for (int q = 0; q < 4; q++) { v[q] = row[lane + 32 * q]; mx = fmaxf(mx, v[q]); }
    #pragma unroll
    for (int o = 16; o; o >>= 1) mx = fmaxf(mx, __shfl_xor_sync(0xffffffffu, mx, o));
    float sum = 0.f;
    #pragma unroll
    for (int q = 0; q < 4; q++) { v[q] = expf(v[q] - mx); sum += v[q]; }
    #pragma unroll
    for (int o = 16; o; o >>= 1) sum += __shfl_xor_sync(0xffffffffu, sum, o);
    #pragma unroll
    for (int q = 0; q < 4; q++) row[lane + 32 * q] = v[q] / sum;
}

// ---------------- Viterbi: one warp-block per batch; OUTPUT AS FLOAT ----------------
__global__ void __launch_bounds__(32) viterbi_kernel(const int* __restrict__ x,
                                                     const float* __restrict__ start_t,
                                                     const float* __restrict__ trans,
                                                     const float* __restrict__ end_t,
                                                     float* __restrict__ out) {
    const int b = blockIdx.x;
    const int j = threadIdx.x;
    __shared__ float esh[S_ * L_];         // [s][l]
    __shared__ float tsh[L_ * L_];
    __shared__ int hist[(S_ - 1) * L_];
    __shared__ unsigned char msk[S_];
    for (int i = j; i < S_ * L_; i += 32) {
        int l = i >> 7, s = i & 127;
        esh[s * L_ + l] = g_em[b * (L_ * S_) + i];
    }
    for (int i = j; i < L_ * L_; i += 32) tsh[i] = trans[i];
    for (int s = j; s < S_; s += 32) msk[s] = (x[b * S_ + s] != 0) ? 1 : 0;
    __syncthreads();
    const int jj = (j < L_) ? j : 0;
    float score = (j < L_) ? (start_t[j] + esh[jj]) : -1e30f;
    for (int s = 1; s < S_; s++) {
        float e = esh[s * L_ + jj];
        float best = -1e30f;
        int arg = 0;
        for (int i = 0; i < L_; i++) {
            float si = __shfl_sync(0xffffffffu, score, i);
            float v = si + tsh[i * L_ + jj];
            if (v > best) { best = v; arg = i; }
        }
        if (j < L_) {
            hist[(s - 1) * L_ + j] = arg;
            if (msk[s]) score = best + e;
        }
    }
    if (j < L_) score += end_t[j];
    float best = -1e30f;
    int last = 0;
    for (int i = 0; i < L_; i++) {
        float si = __shfl_sync(0xffffffffu, score, i);
        if (si > best) { best = si; last = i; }
    }
    if (j == 0) {
        int cur = last;
        out[b * S_ + S_ - 1] = (float)cur;
        for (int s = S_ - 2; s >= 0; s--) {
            if (msk[s + 1]) cur = hist[s * L_ + cur];
            out[b * S_ + s] = (float)cur;
        }
    }
}

// ---------------- launch ----------------
extern "C" void kernel_launch(void* const* d_in, const int* in_sizes, int n_in,
                              void* d_out, int out_size) {
    const int*   x        = (const int*)d_in[0];
    const int*   x_char   = (const int*)d_in[1];
    const float* word_emb = (const float*)d_in[2];
    const float* char_emb = (const float*)d_in[3];
    const float* conv1_w  = (const float*)d_in[4];
    const float* conv1_b  = (const float*)d_in[5];
    const float* conv2_w  = (const float*)d_in[6];
    const float* conv2_b  = (const float*)d_in[7];
    const float* conv3_w  = (const float*)d_in[8];
    const float* conv3_b  = (const float*)d_in[9];
    const float* w_ih_f   = (const float*)d_in[10];
    const float* w_hh_f   = (const float*)d_in[11];
    const float* b_f      = (const float*)d_in[12];
    const float* w_ih_b   = (const float*)d_in[13];
    const float* w_hh_b   = (const float*)d_in[14];
    const float* b_b      = (const float*)d_in[15];
    const float* h0       = (const float*)d_in[16];
    const float* c0       = (const float*)d_in[17];
    const float* fc_w     = (const float*)d_in[18];
    const float* fc_b     = (const float*)d_in[19];
    const float* start_t  = (const float*)d_in[20];
    const float* trans    = (const float*)d_in[21];
    const float* end_t    = (const float*)d_in[22];
    float* out = (float*)d_out;

    conv1_kernel<<<dim3(B_, 4), 128>>>(x_char, char_emb, conv1_w, conv1_b);
    conv2_kernel<<<dim3(B_, 4), 128>>>(conv2_w, conv2_b);
    conv3_kernel<<<dim3(B_, 4), 128>>>(conv3_w, conv3_b);
    gpool_kernel<<<dim3(2, B_), 256>>>(w_ih_f, w_ih_b, b_f, b_b);
    gemm_input_kernel<<<dim3(G4_ / 128, (S_ * B_) / 128, 2), 256>>>(x, word_emb, w_ih_f, w_ih_b);
    cinit_kernel<<<(2 * B_ * H_) / 128, 128>>>(c0);
    for (int t = 0; t < S_; t++)
        lstm_step_kernel<<<dim3(64, 2), 128>>>(w_hh_f, w_hh_b, h0, t);
    fc_kernel<<<S_, 256>>>(fc_w, fc_b);
    softmax_kernel<<<(B_ * L_ * 32 + 255) / 256, 256>>>();
    viterbi_kernel<<<B_, 32>>>(x, start_t, trans, end_t, out);
}

// round 7
// speedup vs baseline: 2.1370x; 2.1370x over previous
#include <cuda_runtime.h>
#include <cuda_bf16.h>
#include <math.h>

// ---------------- problem constants ----------------
#define B_   32
#define S_   128
#define E_   300
#define C_   100
#define EC_  50
#define LC_  50
#define H_   256
#define L_   17
#define G4_  1024          // 4*H
#define D_   400           // E + C

// ---------------- scratch ----------------
__device__ float g_conv1[B_ * C_ * 48];
__device__ float g_conv2[B_ * C_ * 45];
__device__ float g_pooled[B_ * C_];
__device__ float g_gin[2 * S_ * G4_ * B_];              // preactivations [dir][s][r][b]  (TRANSPOSED)
__device__ float g_hseq[2 * S_ * B_ * H_];              // LSTM outputs [dir][s][b][256]
__device__ float g_em[B_ * L_ * S_];                    // emissions [b][l][s]
__device__ unsigned int g_bar;

__device__ __forceinline__ float sigm(float x) { return 1.f / (1.f + expf(-x)); }

// ---------------- char CNN ----------------
__global__ void __launch_bounds__(128) conv1_kernel(const int* __restrict__ xc,
                                                    const float* __restrict__ cemb,
                                                    const float* __restrict__ w1,
                                                    const float* __restrict__ b1) {
    int b = blockIdx.x;
    int oc0 = blockIdx.y * 25;
    __shared__ float ce[EC_][LC_];
    int tid = threadIdx.x;
    for (int i = tid; i < EC_ * LC_; i += 128) {
        int e = i / LC_, t = i % LC_;
        ce[e][t] = cemb[xc[b * LC_ + t] * EC_ + e];
    }
    __syncthreads();
    for (int i = tid; i < 25 * 48; i += 128) {
        int o = i / 48, t = i % 48;
        const float* wr = w1 + (size_t)(oc0 + o) * (EC_ * 3);
        float acc = b1[oc0 + o];
        for (int e = 0; e < EC_; e++) {
            acc += ce[e][t + 0] * wr[e * 3 + 0];
            acc += ce[e][t + 1] * wr[e * 3 + 1];
            acc += ce[e][t + 2] * wr[e * 3 + 2];
        }
        g_conv1[b * (C_ * 48) + (oc0 + o) * 48 + t] = fmaxf(acc, 0.f);
    }
}

__global__ void __launch_bounds__(128) conv2_kernel(const float* __restrict__ w2,
                                                    const float* __restrict__ b2) {
    int b = blockIdx.x;
    int oc0 = blockIdx.y * 25;
    __shared__ float in_s[C_][48];
    int tid = threadIdx.x;
    for (int i = tid; i < C_ * 48; i += 128) ((float*)in_s)[i] = g_conv1[b * (C_ * 48) + i];
    __syncthreads();
    for (int i = tid; i < 25 * 45; i += 128) {
        int o = i / 45, t = i % 45;
        const float* wr = w2 + (size_t)(oc0 + o) * (C_ * 4);
        float acc = b2[oc0 + o];
        for (int ic = 0; ic < C_; ic++) {
            acc += in_s[ic][t + 0] * wr[ic * 4 + 0];
            acc += in_s[ic][t + 1] * wr[ic * 4 + 1];
            acc += in_s[ic][t + 2] * wr[ic * 4 + 2];
            acc += in_s[ic][t + 3] * wr[ic * 4 + 3];
        }
        g_conv2[b * (C_ * 45) + (oc0 + o) * 45 + t] = fmaxf(acc, 0.f);
    }
}

__global__ void __launch_bounds__(128) conv3_kernel(const float* __restrict__ w3,
                                                    const float* __restrict__ b3) {
    int b = blockIdx.x;
    int oc0 = blockIdx.y * 25;
    __shared__ float in_s[C_][45];
    __shared__ float out_s[25][41];
    int tid = threadIdx.x;
    for (int i = tid; i < C_ * 45; i += 128) ((float*)in_s)[i] = g_conv2[b * (C_ * 45) + i];
    __syncthreads();
    for (int i = tid; i < 25 * 41; i += 128) {
        int o = i / 41, t = i % 41;
        const float* wr = w3 + (size_t)(oc0 + o) * (C_ * 5);
        float acc = b3[oc0 + o];
        for (int ic = 0; ic < C_; ic++) {
            acc += in_s[ic][t + 0] * wr[ic * 5 + 0];
            acc += in_s[ic][t + 1] * wr[ic * 5 + 1];
            acc += in_s[ic][t + 2] * wr[ic * 5 + 2];
            acc += in_s[ic][t + 3] * wr[ic * 5 + 3];
            acc += in_s[ic][t + 4] * wr[ic * 5 + 4];
        }
        out_s[o][t] = fmaxf(acc, 0.f);
    }
    __syncthreads();
    if (tid < 25) {
        float m = out_s[tid][0];
        for (int t = 1; t < 41; t++) m = fmaxf(m, out_s[tid][t]);
        g_pooled[b * C_ + oc0 + tid] = m;
    }
}

// ---------------- input GEMM (K=400: word emb 0..299, pooled 300..399) ----------------
// out layout TRANSPOSED: gin[dir][s][r][b]; bias added in epilogue.
__global__ void __launch_bounds__(256) gemm_input_kernel(const int* __restrict__ x,
                                                         const float* __restrict__ word_emb,
                                                         const float* __restrict__ w_ih_f,
                                                         const float* __restrict__ w_ih_b,
                                                         const float* __restrict__ b_f,
                                                         const float* __restrict__ b_b) {
    const int dir = blockIdx.z;
    const float* __restrict__ W = dir ? w_ih_b : w_ih_f;
    const float* __restrict__ bias = dir ? b_b : b_f;
    float* __restrict__ out = g_gin + (size_t)dir * (S_ * G4_ * B_);
    const int m0 = blockIdx.y * 128;
    const int n0 = blockIdx.x * 128;
    __shared__ float As[16][132];
    __shared__ float Bs[16][132];
    __shared__ int wid[128];
    __shared__ float bsh[128];
    const int tid = threadIdx.x;
    if (tid < 128) {
        int m = m0 + tid;
        wid[tid] = x[(m & 31) * S_ + (m >> 5)];   // b = m&31, s = m>>5
        bsh[tid] = bias[n0 + tid];
    }
    __syncthreads();
    const int tx = tid & 15, ty = tid >> 4;
    float acc[8][8];
    #pragma unroll
    for (int i = 0; i < 8; i++)
        #pragma unroll
        for (int j = 0; j < 8; j++) acc[i][j] = 0.f;

    for (int k0 = 0; k0 < 400; k0 += 16) {
        #pragma unroll
        for (int l = 0; l < 2; l++) {
            int idx = tid + l * 256;
            int row = idx >> 2;
            int kq = (idx & 3) * 4;
            int k = k0 + kq;
            float4 av;
            if (k < 300) {
                av = *reinterpret_cast<const float4*>(word_emb + (size_t)wid[row] * E_ + k);
            } else {
                int bb = (m0 + row) & 31;
                av = *reinterpret_cast<const float4*>(g_pooled + bb * C_ + (k - 300));
            }
            As[kq + 0][row] = av.x;
            As[kq + 1][row] = av.y;
            As[kq + 2][row] = av.z;
            As[kq + 3][row] = av.w;
            float4 bv = *reinterpret_cast<const float4*>(W + (size_t)(n0 + row) * D_ + k);
            Bs[kq + 0][row] = bv.x;
            Bs[kq + 1][row] = bv.y;
            Bs[kq + 2][row] = bv.z;
            Bs[kq + 3][row] = bv.w;
        }
        __syncthreads();
        #pragma unroll
        for (int kk = 0; kk < 16; kk++) {
            float a[8], bq[8];
            #pragma unroll
            for (int i = 0; i < 8; i++) a[i] = As[kk][ty * 8 + i];
            #pragma unroll
            for (int j = 0; j < 8; j++) bq[j] = Bs[kk][tx * 8 + j];
            #pragma unroll
            for (int i = 0; i < 8; i++)
                #pragma unroll
                for (int j = 0; j < 8; j++) acc[i][j] += a[i] * bq[j];
        }
        __syncthreads();
    }
    #pragma unroll
    for (int i = 0; i < 8; i++) {
        int m = m0 + ty * 8 + i;
        int s = m >> 5;
        int bb = m & 31;
        float* obase = out + (size_t)s * (G4_ * B_) + bb;
        #pragma unroll
        for (int j = 0; j < 8; j++) {
            int n = n0 + tx * 8 + j;
            obase[(size_t)n * B_] = acc[i][j] + bsh[tx * 8 + j];
        }
    }
}

// ---------------- persistent bidirectional LSTM ----------------
__global__ void zero_bar_kernel() { g_bar = 0u; }

// CG-style grid barrier: release on arrival, acquire on observation.
__device__ __forceinline__ void grid_barrier(unsigned int target) {
    __threadfence();
    __syncthreads();
    if (threadIdx.x == 0) {
        asm volatile("red.release.gpu.global.add.u32 [%0], 1;"
                     :: "l"(&g_bar) : "memory");
        unsigned int v;
        do {
            asm volatile("ld.acquire.gpu.global.u32 %0, [%1];"
                         : "=r"(v) : "l"(&g_bar) : "memory");
        } while (v < target);
        __threadfence();
    }
    __syncthreads();
}

__global__ void __launch_bounds__(256) lstm_persist_kernel(const float* __restrict__ w_hh_f,
                                                           const float* __restrict__ w_hh_b,
                                                           const float* __restrict__ h0,
                                                           const float* __restrict__ c0) {
    const int dir = blockIdx.x >> 6;       // 64 blocks per direction
    const int blk = blockIdx.x & 63;
    const int j0 = blk * 4;                // 4 hidden units per block
    const float* __restrict__ W = dir ? w_hh_b : w_hh_f;
    __shared__ float wsh[16][256];         // [r=gate*4+u][k]
    __shared__ float hs[32][260];          // [b][k], k=0..255, pad 4 -> conflict-free LDS.128
    __shared__ float gsh[16][33];          // gate outputs [r][b]
    __shared__ float csh[4][32];           // cell state [u][b]
    const int tid = threadIdx.x;
    for (int i = tid; i < 16 * 256; i += 256) {
        int r = i >> 8, k = i & 255;
        int row = (r >> 2) * H_ + j0 + (r & 3);
        wsh[r][k] = W[(size_t)row * H_ + k];
    }
    if (tid < 128) {
        int u = tid >> 5, b = tid & 31;
        csh[u][b] = c0[dir * (B_ * H_) + b * H_ + j0 + u];
    }
    __syncthreads();

    float* __restrict__ hseq = g_hseq + (size_t)dir * (S_ * B_ * H_);
    const float* __restrict__ gin = g_gin + (size_t)dir * (S_ * G4_ * B_);
    const int wd = tid >> 5;               // warp 0..7
    const int lane = tid & 31;             // = batch
    const int r0 = 2 * wd, r1 = r0 + 1;
    const int rg0 = (r0 >> 2) * H_ + j0 + (r0 & 3);
    const int rg1 = (r1 >> 2) * H_ + j0 + (r1 & 3);

    for (int t = 0; t < S_; t++) {
        const int s = dir ? (S_ - 1 - t) : t;
        const int sp = dir ? (s + 1) : (s - 1);
        const float* hprev = (t == 0) ? (h0 + dir * (B_ * H_))
                                      : (hseq + (size_t)sp * (B_ * H_));
        // stage h -> smem (coherent loads: data written by other blocks intra-kernel)
        const float4* hp4 = (const float4*)hprev;
        #pragma unroll
        for (int i = 0; i < 8; i++) {
            int idx = tid + i * 256;
            int b = idx >> 6, kq = idx & 63;
            float4 v = __ldcg(&hp4[idx]);
            *(float4*)&hs[b][kq * 4] = v;
        }
        __syncthreads();

        float a00 = 0.f, a01 = 0.f, a02 = 0.f, a03 = 0.f;
        float a10 = 0.f, a11 = 0.f, a12 = 0.f, a13 = 0.f;
        #pragma unroll 8
        for (int kq = 0; kq < 64; kq++) {
            float4 h4 = *(float4*)&hs[lane][kq * 4];
            float4 w0 = *(float4*)&wsh[r0][kq * 4];
            float4 w1 = *(float4*)&wsh[r1][kq * 4];
            a00 += w0.x * h4.x; a01 += w0.y * h4.y;
            a02 += w0.z * h4.z; a03 += w0.w * h4.w;
            a10 += w1.x * h4.x; a11 += w1.y * h4.y;
            a12 += w1.z * h4.z; a13 += w1.w * h4.w;
        }
        const float* grow = gin + (size_t)s * (G4_ * B_);
        float acc0 = (a00 + a01) + (a02 + a03) + __ldg(&grow[rg0 * B_ + lane]);
        float acc1 = (a10 + a11) + (a12 + a13) + __ldg(&grow[rg1 * B_ + lane]);
        gsh[r0][lane] = acc0;
        gsh[r1][lane] = acc1;
        __syncthreads();
        if (tid < 128) {
            int u = tid >> 5, b = tid & 31;
            float gi = gsh[u][b];
            float gf = gsh[4 + u][b];
            float gg = gsh[8 + u][b];
            float go = gsh[12 + u][b];
            float c = sigm(gf) * csh[u][b] + sigm(gi) * tanhf(gg);
            csh[u][b] = c;
            __stcg(&hseq[(size_t)s * (B_ * H_) + b * H_ + j0 + u], sigm(go) * tanhf(c));
        }
        grid_barrier(128u * (unsigned)(t + 1));
    }
}

// ---------------- fc -> emission logits (layout [b][l][s]) ----------------
__global__ void __launch_bounds__(256) fc_kernel(const float* __restrict__ fc_w,
                                                 const float* __restrict__ fc_b) {
    const int s = blockIdx.x;
    __shared__ float ws[L_ * 512];
    const int tid = threadIdx.x;
    for (int i = tid; i < L_ * 512; i += 256) ws[i] = fc_w[i];
    __syncthreads();
    const float* hf = g_hseq + (size_t)s * (B_ * H_);
    const float* hb = g_hseq + (size_t)(S_ * B_ * H_) + (size_t)s * (B_ * H_);
    for (int idx = tid; idx < B_ * L_; idx += 256) {
        int b = idx / L_, l = idx % L_;
        const float4* hf4 = (const float4*)(hf + b * H_);
        const float4* hb4 = (const float4*)(hb + b * H_);
        const float4* w0 = (const float4*)(ws + l * 512);
        const float4* w1 = w0 + 64;
        float acc = fc_b[l];
        #pragma unroll 8
        for (int k = 0; k < 64; k++) {
            float4 h4 = hf4[k], w4 = w0[k];
            acc += h4.x * w4.x + h4.y * w4.y + h4.z * w4.z + h4.w * w4.w;
            float4 h5 = hb4[k], w5 = w1[k];
            acc += h5.x * w5.x + h5.y * w5.y + h5.z * w5.z + h5.w * w5.w;
        }
        g_em[b * (L_ * S_) + l * S_ + s] = acc;
    }
}

// ---------------- softmax over seq dim ----------------
__global__ void __launch_bounds__(256) softmax_kernel() {
    int w = (blockIdx.x * 256 + threadIdx.x) >> 5;
    int lane = threadIdx.x & 31;
    if (w >= B_ * L_) return;
    float* row = g_em + (size_t)w * S_;
    float v[4];
    float mx = -1e30f;
    #pragma unroll
    for (int q = 0; q < 4; q++) { v[q] = row[lane + 32 * q]; mx = fmaxf(mx, v[q]); }
    #pragma unroll
    for (int o = 16; o; o >>= 1) mx = fmaxf(mx, __shfl_xor_sync(0xffffffffu, mx, o));
    float sum = 0.f;
    #pragma unroll
    for (int q = 0; q < 4; q++) { v[q] = expf(v[q] - mx); sum += v[q]; }
    #pragma unroll
    for (int o = 16; o; o >>= 1) sum += __shfl_xor_sync(0xffffffffu, sum, o);
    #pragma unroll
    for (int q = 0; q < 4; q++) row[lane + 32 * q] = v[q] / sum;
}

// ---------------- Viterbi: one warp-block per batch; float output ----------------
__global__ void __launch_bounds__(32) viterbi_kernel(const int* __restrict__ x,
                                                     const float* __restrict__ start_t,
                                                     const float* __restrict__ trans,
                                                     const float* __restrict__ end_t,
                                                     float* __restrict__ out) {
    const int b = blockIdx.x;
    const int j = threadIdx.x;
    __shared__ float esh[S_ * L_];         // [s][l]
    __shared__ float tsh[L_ * L_];
    __shared__ int hist[(S_ - 1) * L_];
    __shared__ unsigned char msk[S_];
    for (int i = j; i < S_ * L_; i += 32) {
        int l = i >> 7, s = i & 127;
        esh[s * L_ + l] = g_em[b * (L_ * S_) + i];
    }
    for (int i = j; i < L_ * L_; i += 32) tsh[i] = trans[i];
    for (int s = j; s < S_; s += 32) msk[s] = (x[b * S_ + s] != 0) ? 1 : 0;
    __syncthreads();
    const int jj = (j < L_) ? j : 0;
    float score = (j < L_) ? (start_t[j] + esh[jj]) : -1e30f;
    for (int s = 1; s < S_; s++) {
        float e = esh[s * L_ + jj];
        float best = -1e30f;
        int arg = 0;
        for (int i = 0; i < L_; i++) {
            float si = __shfl_sync(0xffffffffu, score, i);
            float v = si + tsh[i * L_ + jj];
            if (v > best) { best = v; arg = i; }
        }
        if (j < L_) {
            hist[(s - 1) * L_ + j] = arg;
            if (msk[s]) score = best + e;
        }
    }
    if (j < L_) score += end_t[j];
    float best = -1e30f;
    int last = 0;
    for (int i = 0; i < L_; i++) {
        float si = __shfl_sync(0xffffffffu, score, i);
        if (si > best) { best = si; last = i; }
    }
    if (j == 0) {
        int cur = last;
        out[b * S_ + S_ - 1] = (float)cur;
        for (int s = S_ - 2; s >= 0; s--) {
            if (msk[s + 1]) cur = hist[s * L_ + cur];
            out[b * S_ + s] = (float)cur;
        }
    }
}

// ---------------- launch ----------------
extern "C" void kernel_launch(void* const* d_in, const int* in_sizes, int n_in,
                              void* d_out, int out_size) {
    const int*   x        = (const int*)d_in[0];
    const int*   x_char   = (const int*)d_in[1];
    const float* word_emb = (const float*)d_in[2];
    const float* char_emb = (const float*)d_in[3];
    const float* conv1_w  = (const float*)d_in[4];
    const float* conv1_b  = (const float*)d_in[5];
    const float* conv2_w  = (const float*)d_in[6];
    const float* conv2_b  = (const float*)d_in[7];
    const float* conv3_w  = (const float*)d_in[8];
    const float* conv3_b  = (const float*)d_in[9];
    const float* w_ih_f   = (const float*)d_in[10];
    const float* w_hh_f   = (const float*)d_in[11];
    const float* b_f      = (const float*)d_in[12];
    const float* w_ih_b   = (const float*)d_in[13];
    const float* w_hh_b   = (const float*)d_in[14];
    const float* b_b      = (const float*)d_in[15];
    const float* h0       = (const float*)d_in[16];
    const float* c0       = (const float*)d_in[17];
    const float* fc_w     = (const float*)d_in[18];
    const float* fc_b     = (const float*)d_in[19];
    const float* start_t  = (const float*)d_in[20];
    const float* trans    = (const float*)d_in[21];
    const float* end_t    = (const float*)d_in[22];
    float* out = (float*)d_out;

    conv1_kernel<<<dim3(B_, 4), 128>>>(x_char, char_emb, conv1_w, conv1_b);
    conv2_kernel<<<dim3(B_, 4), 128>>>(conv2_w, conv2_b);
    conv3_kernel<<<dim3(B_, 4), 128>>>(conv3_w, conv3_b);
    gemm_input_kernel<<<dim3(G4_ / 128, (S_ * B_) / 128, 2), 256>>>(x, word_emb, w_ih_f, w_ih_b, b_f, b_b);
    zero_bar_kernel<<<1, 1>>>();
    lstm_persist_kernel<<<128, 256>>>(w_hh_f, w_hh_b, h0, c0);
    fc_kernel<<<S_, 256>>>(fc_w, fc_b);
    softmax_kernel<<<(B_ * L_ * 32 + 255) / 256, 256>>>();
    viterbi_kernel<<<B_, 32>>>(x, start_t, trans, end_t, out);
}

// round 8
// speedup vs baseline: 2.3393x; 1.0947x over previous
#include <cuda_runtime.h>
#include <cuda_bf16.h>
#include <math.h>

// ---------------- problem constants ----------------
#define B_   32
#define S_   128
#define E_   300
#define C_   100
#define EC_  50
#define LC_  50
#define H_   256
#define L_   17
#define G4_  1024          // 4*H
#define D_   400           // E + C

// ---------------- scratch ----------------
__device__ float g_conv1[B_ * C_ * 48];
__device__ float g_conv2[B_ * C_ * 45];
__device__ float g_pooled[B_ * C_];
__device__ float g_gin[2 * S_ * G4_ * B_];              // preactivations [dir][s][r][b]  (TRANSPOSED)
__device__ float g_hseq[2 * S_ * B_ * H_];              // LSTM outputs [dir][s][b][256]
__device__ float g_em[B_ * L_ * S_];                    // emissions [b][l][s]
__device__ unsigned int g_bar;

__device__ __forceinline__ float sigm(float x) { return 1.f / (1.f + expf(-x)); }

// ---------------- char CNN ----------------
__global__ void __launch_bounds__(128) conv1_kernel(const int* __restrict__ xc,
                                                    const float* __restrict__ cemb,
                                                    const float* __restrict__ w1,
                                                    const float* __restrict__ b1) {
    int b = blockIdx.x;
    int oc0 = blockIdx.y * 25;
    __shared__ float ce[EC_][LC_];
    int tid = threadIdx.x;
    for (int i = tid; i < EC_ * LC_; i += 128) {
        int e = i / LC_, t = i % LC_;
        ce[e][t] = cemb[xc[b * LC_ + t] * EC_ + e];
    }
    __syncthreads();
    for (int i = tid; i < 25 * 48; i += 128) {
        int o = i / 48, t = i % 48;
        const float* wr = w1 + (size_t)(oc0 + o) * (EC_ * 3);
        float acc = b1[oc0 + o];
        for (int e = 0; e < EC_; e++) {
            acc += ce[e][t + 0] * wr[e * 3 + 0];
            acc += ce[e][t + 1] * wr[e * 3 + 1];
            acc += ce[e][t + 2] * wr[e * 3 + 2];
        }
        g_conv1[b * (C_ * 48) + (oc0 + o) * 48 + t] = fmaxf(acc, 0.f);
    }
}

__global__ void __launch_bounds__(128) conv2_kernel(const float* __restrict__ w2,
                                                    const float* __restrict__ b2) {
    int b = blockIdx.x;
    int oc0 = blockIdx.y * 25;
    __shared__ float in_s[C_][48];
    int tid = threadIdx.x;
    for (int i = tid; i < C_ * 48; i += 128) ((float*)in_s)[i] = g_conv1[b * (C_ * 48) + i];
    __syncthreads();
    for (int i = tid; i < 25 * 45; i += 128) {
        int o = i / 45, t = i % 45;
        const float* wr = w2 + (size_t)(oc0 + o) * (C_ * 4);
        float acc = b2[oc0 + o];
        for (int ic = 0; ic < C_; ic++) {
            acc += in_s[ic][t + 0] * wr[ic * 4 + 0];
            acc += in_s[ic][t + 1] * wr[ic * 4 + 1];
            acc += in_s[ic][t + 2] * wr[ic * 4 + 2];
            acc += in_s[ic][t + 3] * wr[ic * 4 + 3];
        }
        g_conv2[b * (C_ * 45) + (oc0 + o) * 45 + t] = fmaxf(acc, 0.f);
    }
}

__global__ void __launch_bounds__(128) conv3_kernel(const float* __restrict__ w3,
                                                    const float* __restrict__ b3) {
    int b = blockIdx.x;
    int oc0 = blockIdx.y * 25;
    __shared__ float in_s[C_][45];
    __shared__ float out_s[25][41];
    int tid = threadIdx.x;
    for (int i = tid; i < C_ * 45; i += 128) ((float*)in_s)[i] = g_conv2[b * (C_ * 45) + i];
    __syncthreads();
    for (int i = tid; i < 25 * 41; i += 128) {
        int o = i / 41, t = i % 41;
        const float* wr = w3 + (size_t)(oc0 + o) * (C_ * 5);
        float acc = b3[oc0 + o];
        for (int ic = 0; ic < C_; ic++) {
            acc += in_s[ic][t + 0] * wr[ic * 5 + 0];
            acc += in_s[ic][t + 1] * wr[ic * 5 + 1];
            acc += in_s[ic][t + 2] * wr[ic * 5 + 2];
            acc += in_s[ic][t + 3] * wr[ic * 5 + 3];
            acc += in_s[ic][t + 4] * wr[ic * 5 + 4];
        }
        out_s[o][t] = fmaxf(acc, 0.f);
    }
    __syncthreads();
    if (tid < 25) {
        float m = out_s[tid][0];
        for (int t = 1; t < 41; t++) m = fmaxf(m, out_s[tid][t]);
        g_pooled[b * C_ + oc0 + tid] = m;
    }
}

// ---------------- input GEMM (K=400: word emb 0..299, pooled 300..399) ----------------
__global__ void __launch_bounds__(256) gemm_input_kernel(const int* __restrict__ x,
                                                         const float* __restrict__ word_emb,
                                                         const float* __restrict__ w_ih_f,
                                                         const float* __restrict__ w_ih_b,
                                                         const float* __restrict__ b_f,
                                                         const float* __restrict__ b_b) {
    const int dir = blockIdx.z;
    const float* __restrict__ W = dir ? w_ih_b : w_ih_f;
    const float* __restrict__ bias = dir ? b_b : b_f;
    float* __restrict__ out = g_gin + (size_t)dir * (S_ * G4_ * B_);
    const int m0 = blockIdx.y * 128;
    const int n0 = blockIdx.x * 128;
    __shared__ float As[16][132];
    __shared__ float Bs[16][132];
    __shared__ int wid[128];
    __shared__ float bsh[128];
    const int tid = threadIdx.x;
    if (tid < 128) {
        int m = m0 + tid;
        wid[tid] = x[(m & 31) * S_ + (m >> 5)];   // b = m&31, s = m>>5
        bsh[tid] = bias[n0 + tid];
    }
    __syncthreads();
    const int tx = tid & 15, ty = tid >> 4;
    float acc[8][8];
    #pragma unroll
    for (int i = 0; i < 8; i++)
        #pragma unroll
        for (int j = 0; j < 8; j++) acc[i][j] = 0.f;

    for (int k0 = 0; k0 < 400; k0 += 16) {
        #pragma unroll
        for (int l = 0; l < 2; l++) {
            int idx = tid + l * 256;
            int row = idx >> 2;
            int kq = (idx & 3) * 4;
            int k = k0 + kq;
            float4 av;
            if (k < 300) {
                av = *reinterpret_cast<const float4*>(word_emb + (size_t)wid[row] * E_ + k);
            } else {
                int bb = (m0 + row) & 31;
                av = *reinterpret_cast<const float4*>(g_pooled + bb * C_ + (k - 300));
            }
            As[kq + 0][row] = av.x;
            As[kq + 1][row] = av.y;
            As[kq + 2][row] = av.z;
            As[kq + 3][row] = av.w;
            float4 bv = *reinterpret_cast<const float4*>(W + (size_t)(n0 + row) * D_ + k);
            Bs[kq + 0][row] = bv.x;
            Bs[kq + 1][row] = bv.y;
            Bs[kq + 2][row] = bv.z;
            Bs[kq + 3][row] = bv.w;
        }
        __syncthreads();
        #pragma unroll
        for (int kk = 0; kk < 16; kk++) {
            float a[8], bq[8];
            #pragma unroll
            for (int i = 0; i < 8; i++) a[i] = As[kk][ty * 8 + i];
            #pragma unroll
            for (int j = 0; j < 8; j++) bq[j] = Bs[kk][tx * 8 + j];
            #pragma unroll
            for (int i = 0; i < 8; i++)
                #pragma unroll
                for (int j = 0; j < 8; j++) acc[i][j] += a[i] * bq[j];
        }
        __syncthreads();
    }
    #pragma unroll
    for (int i = 0; i < 8; i++) {
        int m = m0 + ty * 8 + i;
        int s = m >> 5;
        int bb = m & 31;
        float* obase = out + (size_t)s * (G4_ * B_) + bb;
        #pragma unroll
        for (int j = 0; j < 8; j++) {
            int n = n0 + tx * 8 + j;
            obase[(size_t)n * B_] = acc[i][j] + bsh[tx * 8 + j];
        }
    }
}

// ---------------- persistent bidirectional LSTM ----------------
__global__ void zero_bar_kernel() { g_bar = 0u; }

__device__ __forceinline__ void grid_barrier(unsigned int target) {
    __threadfence();
    __syncthreads();
    if (threadIdx.x == 0) {
        asm volatile("red.release.gpu.global.add.u32 [%0], 1;"
                     :: "l"(&g_bar) : "memory");
        unsigned int v;
        do {
            asm volatile("ld.acquire.gpu.global.u32 %0, [%1];"
                         : "=r"(v) : "l"(&g_bar) : "memory");
        } while (v < target);
        __threadfence();
    }
    __syncthreads();
}

// 128 blocks (64/dir), 256 thr. Warp = (K-half, row-quad): 4 gate rows over 128 K.
__global__ void __launch_bounds__(256) lstm_persist_kernel(const float* __restrict__ w_hh_f,
                                                           const float* __restrict__ w_hh_b,
                                                           const float* __restrict__ h0,
                                                           const float* __restrict__ c0) {
    const int dir = blockIdx.x >> 6;
    const int blk = blockIdx.x & 63;
    const int j0 = blk * 4;                // 4 hidden units per block
    const float* __restrict__ W = dir ? w_hh_b : w_hh_f;
    __shared__ float wsh[16][256];         // [rr = gate*4+unit][k]
    __shared__ float hs[32][260];          // [b][k], +4 pad -> conflict-free LDS.128
    __shared__ float psh[2][16][33];       // K-half partials [kh][rr][b]
    __shared__ float csh[4][32];           // cell state [u][b]
    const int tid = threadIdx.x;
    for (int i = tid; i < 16 * 256; i += 256) {
        int r = i >> 8, k = i & 255;
        int row = (r >> 2) * H_ + j0 + (r & 3);
        wsh[r][k] = W[(size_t)row * H_ + k];
    }
    if (tid < 128) {
        int u = tid >> 5, b = tid & 31;
        csh[u][b] = c0[dir * (B_ * H_) + b * H_ + j0 + u];
    }
    __syncthreads();

    float* __restrict__ hseq = g_hseq + (size_t)dir * (S_ * B_ * H_);
    const float* __restrict__ gin = g_gin + (size_t)dir * (S_ * G4_ * B_);
    const int wd = tid >> 5;               // warp 0..7
    const int lane = tid & 31;             // batch
    const int kh = wd >> 2;                // K-half (0: k<128, 1: k>=128)
    const int rq = wd & 3;                 // row quad -> rows rq*4 .. rq*4+3
    const int kbase = kh * 128;
    const int r0 = rq * 4;
    const int cu = tid >> 5;               // combine role: unit (valid when tid<128)

    for (int t = 0; t < S_; t++) {
        const int s = dir ? (S_ - 1 - t) : t;
        const int sp = dir ? (s + 1) : (s - 1);
        const float* hprev = (t == 0) ? (h0 + dir * (B_ * H_))
                                      : (hseq + (size_t)sp * (B_ * H_));
        // prefetch gin for the combine stage (independent of h)
        const float* grow = gin + (size_t)s * (G4_ * B_);
        float gpre0 = 0.f, gpre1 = 0.f, gpre2 = 0.f, gpre3 = 0.f;
        if (tid < 128) {
            gpre0 = __ldg(&grow[(0 * H_ + j0 + cu) * B_ + lane]);
            gpre1 = __ldg(&grow[(1 * H_ + j0 + cu) * B_ + lane]);
            gpre2 = __ldg(&grow[(2 * H_ + j0 + cu) * B_ + lane]);
            gpre3 = __ldg(&grow[(3 * H_ + j0 + cu) * B_ + lane]);
        }
        // stage h -> smem (coherent: written by other blocks intra-kernel)
        const float4* hp4 = (const float4*)hprev;
        #pragma unroll
        for (int i = 0; i < 8; i++) {
            int idx = tid + i * 256;
            int b = idx >> 6, kq = idx & 63;
            float4 v = __ldcg(&hp4[idx]);
            *(float4*)&hs[b][kq * 4] = v;
        }
        __syncthreads();

        // 4 rows x half-K partial dot
        float a0 = 0.f, a1 = 0.f, a2 = 0.f, a3 = 0.f;
        float c0v = 0.f, c1v = 0.f, c2v = 0.f, c3v = 0.f;
        #pragma unroll 8
        for (int kq = 0; kq < 32; kq++) {
            float4 h4 = *(const float4*)&hs[lane][kbase + kq * 4];
            float4 w0 = *(const float4*)&wsh[r0 + 0][kbase + kq * 4];
            a0 += w0.x * h4.x + w0.y * h4.y;  c0v += w0.z * h4.z + w0.w * h4.w;
            float4 w1 = *(const float4*)&wsh[r0 + 1][kbase + kq * 4];
            a1 += w1.x * h4.x + w1.y * h4.y;  c1v += w1.z * h4.z + w1.w * h4.w;
            float4 w2 = *(const float4*)&wsh[r0 + 2][kbase + kq * 4];
            a2 += w2.x * h4.x + w2.y * h4.y;  c2v += w2.z * h4.z + w2.w * h4.w;
            float4 w3 = *(const float4*)&wsh[r0 + 3][kbase + kq * 4];
            a3 += w3.x * h4.x + w3.y * h4.y;  c3v += w3.z * h4.z + w3.w * h4.w;
        }
        psh[kh][r0 + 0][lane] = a0 + c0v;
        psh[kh][r0 + 1][lane] = a1 + c1v;
        psh[kh][r0 + 2][lane] = a2 + c2v;
        psh[kh][r0 + 3][lane] = a3 + c3v;
        __syncthreads();

        if (tid < 128) {
            int u = cu, b = lane;
            float gi = psh[0][0 * 4 + u][b] + psh[1][0 * 4 + u][b] + gpre0;
            float gf = psh[0][1 * 4 + u][b] + psh[1][1 * 4 + u][b] + gpre1;
            float gg = psh[0][2 * 4 + u][b] + psh[1][2 * 4 + u][b] + gpre2;
            float go = psh[0][3 * 4 + u][b] + psh[1][3 * 4 + u][b] + gpre3;
            float c = sigm(gf) * csh[u][b] + sigm(gi) * tanhf(gg);
            csh[u][b] = c;
            __stcg(&hseq[(size_t)s * (B_ * H_) + b * H_ + j0 + u], sigm(go) * tanhf(c));
        }
        grid_barrier(128u * (unsigned)(t + 1));
    }
}

// ---------------- fc -> emission logits (layout [b][l][s]) ----------------
__global__ void __launch_bounds__(256) fc_kernel(const float* __restrict__ fc_w,
                                                 const float* __restrict__ fc_b) {
    const int s = blockIdx.x;
    __shared__ float ws[L_ * 512];
    const int tid = threadIdx.x;
    for (int i = tid; i < L_ * 512; i += 256) ws[i] = fc_w[i];
    __syncthreads();
    const float* hf = g_hseq + (size_t)s * (B_ * H_);
    const float* hb = g_hseq + (size_t)(S_ * B_ * H_) + (size_t)s * (B_ * H_);
    for (int idx = tid; idx < B_ * L_; idx += 256) {
        int b = idx / L_, l = idx % L_;
        const float4* hf4 = (const float4*)(hf + b * H_);
        const float4* hb4 = (const float4*)(hb + b * H_);
        const float4* w0 = (const float4*)(ws + l * 512);
        const float4* w1 = w0 + 64;
        float acc = fc_b[l];
        #pragma unroll 8
        for (int k = 0; k < 64; k++) {
            float4 h4 = hf4[k], w4 = w0[k];
            acc += h4.x * w4.x + h4.y * w4.y + h4.z * w4.z + h4.w * w4.w;
            float4 h5 = hb4[k], w5 = w1[k];
            acc += h5.x * w5.x + h5.y * w5.y + h5.z * w5.z + h5.w * w5.w;
        }
        g_em[b * (L_ * S_) + l * S_ + s] = acc;
    }
}

// ---------------- softmax over seq dim ----------------
__global__ void __launch_bounds__(256) softmax_kernel() {
    int w = (blockIdx.x * 256 + threadIdx.x) >> 5;
    int lane = threadIdx.x & 31;
    if (w >= B_ * L_) return;
    float* row = g_em + (size_t)w * S_;
    float v[4];
    float mx = -1e30f;
    #pragma unroll
    for (int q = 0; q < 4; q++) { v[q] = row[lane + 32 * q]; mx = fmaxf(mx, v[q]); }
    #pragma unroll
    for (int o = 16; o; o >>= 1) mx = fmaxf(mx, __shfl_xor_sync(0xffffffffu, mx, o));
    float sum = 0.f;
    #pragma unroll
    for (int q = 0; q < 4; q++) { v[q] = expf(v[q] - mx); sum += v[q]; }
    #pragma unroll
    for (int o = 16; o; o >>= 1) sum += __shfl_xor_sync(0xffffffffu, sum, o);
    #pragma unroll
    for (int q = 0; q < 4; q++) row[lane + 32 * q] = v[q] / sum;
}

// ---------------- Viterbi: one warp-block per batch; float output ----------------
__global__ void __launch_bounds__(32) viterbi_kernel(const int* __restrict__ x,
                                                     const float* __restrict__ start_t,
                                                     const float* __restrict__ trans,
                                                     const float* __restrict__ end_t,
                                                     float* __restrict__ out) {
    const int b = blockIdx.x;
    const int j = threadIdx.x;
    __shared__ float esh[S_ * L_];         // [s][l]
    __shared__ float tsh[L_ * L_];
    __shared__ int hist[(S_ - 1) * L_];
    __shared__ unsigned char msk[S_];
    for (int i = j; i < S_ * L_; i += 32) {
        int l = i >> 7, s = i & 127;
        esh[s * L_ + l] = g_em[b * (L_ * S_) + i];
    }
    for (int i = j; i < L_ * L_; i += 32) tsh[i] = trans[i];
    for (int s = j; s < S_; s += 32) msk[s] = (x[b * S_ + s] != 0) ? 1 : 0;
    __syncthreads();
    const int jj = (j < L_) ? j : 0;
    float score = (j < L_) ? (start_t[j] + esh[jj]) : -1e30f;
    for (int s = 1; s < S_; s++) {
        float e = esh[s * L_ + jj];
        float best = -1e30f;
        int arg = 0;
        for (int i = 0; i < L_; i++) {
            float si = __shfl_sync(0xffffffffu, score, i);
            float v = si + tsh[i * L_ + jj];
            if (v > best) { best = v; arg = i; }
        }
        if (j < L_) {
            hist[(s - 1) * L_ + j] = arg;
            if (msk[s]) score = best + e;
        }
    }
    if (j < L_) score += end_t[j];
    float best = -1e30f;
    int last = 0;
    for (int i = 0; i < L_; i++) {
        float si = __shfl_sync(0xffffffffu, score, i);
        if (si > best) { best = si; last = i; }
    }
    if (j == 0) {
        int cur = last;
        out[b * S_ + S_ - 1] = (float)cur;
        for (int s = S_ - 2; s >= 0; s--) {
            if (msk[s + 1]) cur = hist[s * L_ + cur];
            out[b * S_ + s] = (float)cur;
        }
    }
}

// ---------------- launch ----------------
extern "C" void kernel_launch(void* const* d_in, const int* in_sizes, int n_in,
                              void* d_out, int out_size) {
    const int*   x        = (const int*)d_in[0];
    const int*   x_char   = (const int*)d_in[1];
    const float* word_emb = (const float*)d_in[2];
    const float* char_emb = (const float*)d_in[3];
    const float* conv1_w  = (const float*)d_in[4];
    const float* conv1_b  = (const float*)d_in[5];
    const float* conv2_w  = (const float*)d_in[6];
    const float* conv2_b  = (const float*)d_in[7];
    const float* conv3_w  = (const float*)d_in[8];
    const float* conv3_b  = (const float*)d_in[9];
    const float* w_ih_f   = (const float*)d_in[10];
    const float* w_hh_f   = (const float*)d_in[11];
    const float* b_f      = (const float*)d_in[12];
    const float* w_ih_b   = (const float*)d_in[13];
    const float* w_hh_b   = (const float*)d_in[14];
    const float* b_b      = (const float*)d_in[15];
    const float* h0       = (const float*)d_in[16];
    const float* c0       = (const float*)d_in[17];
    const float* fc_w     = (const float*)d_in[18];
    const float* fc_b     = (const float*)d_in[19];
    const float* start_t  = (const float*)d_in[20];
    const float* trans    = (const float*)d_in[21];
    const float* end_t    = (const float*)d_in[22];
    float* out = (float*)d_out;

    conv1_kernel<<<dim3(B_, 4), 128>>>(x_char, char_emb, conv1_w, conv1_b);
    conv2_kernel<<<dim3(B_, 4), 128>>>(conv2_w, conv2_b);
    conv3_kernel<<<dim3(B_, 4), 128>>>(conv3_w, conv3_b);
    gemm_input_kernel<<<dim3(G4_ / 128, (S_ * B_) / 128, 2), 256>>>(x, word_emb, w_ih_f, w_ih_b, b_f, b_b);
    zero_bar_kernel<<<1, 1>>>();
    lstm_persist_kernel<<<128, 256>>>(w_hh_f, w_hh_b, h0, c0);
    fc_kernel<<<S_, 256>>>(fc_w, fc_b);
    softmax_kernel<<<(B_ * L_ * 32 + 255) / 256, 256>>>();
    viterbi_kernel<<<B_, 32>>>(x, start_t, trans, end_t, out);
}